// round 15
// baseline (speedup 1.0000x reference)
#include <cuda_runtime.h>
#include <cuda_fp16.h>
#include <cstdint>

// CodeBook VQ argmin: one-pass fp16 HMMA screen + exact rescue.
// R15: MCTA=128 with 2 CTAs/SM (smem 112KB, 64-reg budget): co-resident CTAs
// overlap head/tail with mainloop and remove the 4-wave ceil quantization.
//   d_hi[k] = e2[k] - 2*(Xhi·Ehi^T);  candidates: d_hi <= running_min + DELTA
//   rescue: exact fp32 dot (z from gmem, emb fp32), tie -> lowest code.

#define NCODES 1024
#define KDIM   256
#define NPIX   4096
#define MCTA   128
#define DELTA  0.5f
#define LCAP   12

#define ASTR   264              // A row stride halves (528B)
#define BSTR   72               // B row stride halves (144B)
#define BK     64
#define NTILE  32               // 8 nchunks x 4 ktiles
#define BBUF_SZ 18432

#define AHI_OFF   0             // 128*528 = 67584
#define B_OFF     67584         // 2 x 18432 = 36864
#define MK_OFF    104448        // 128*8 = 1024
#define CNT_OFF   105472        // 512
#define LST_OFF   105984        // 128*12*4 = 6144
#define SMEM_SZ   112128

__device__ __align__(16) __half g_Ehi[NCODES * KDIM];
__device__ float g_e2[NCODES];

__device__ __forceinline__ void ldmx4(uint32_t* r, uint32_t addr) {
    asm volatile("ldmatrix.sync.aligned.m8n8.x4.shared.b16 {%0,%1,%2,%3}, [%4];"
                 : "=r"(r[0]), "=r"(r[1]), "=r"(r[2]), "=r"(r[3]) : "r"(addr));
}
__device__ __forceinline__ void mma16816(float* c, const uint32_t* a, uint32_t b0, uint32_t b1) {
    asm volatile("mma.sync.aligned.m16n8k16.row.col.f32.f16.f16.f32 "
                 "{%0,%1,%2,%3}, {%4,%5,%6,%7}, {%8,%9}, {%0,%1,%2,%3};"
                 : "+f"(c[0]), "+f"(c[1]), "+f"(c[2]), "+f"(c[3])
                 : "r"(a[0]), "r"(a[1]), "r"(a[2]), "r"(a[3]), "r"(b0), "r"(b1));
}
__device__ __forceinline__ void cp16(uint32_t dst, const void* src) {
    asm volatile("cp.async.cg.shared.global [%0], [%1], 16;"
                 :: "r"(dst), "l"(__cvta_generic_to_global(src)) : "memory");
}
#define CP_COMMIT() asm volatile("cp.async.commit_group;" ::: "memory")
#define CP_WAIT1()  asm volatile("cp.async.wait_group 1;" ::: "memory")
#define CP_WAIT0()  asm volatile("cp.async.wait_group 0;" ::: "memory")

__device__ __forceinline__ unsigned long long dkey(float d, int code) {
    uint32_t b = __float_as_uint(d);
    b = (b & 0x80000000u) ? ~b : (b | 0x80000000u);
    return ((unsigned long long)b << 32) | (unsigned)code;
}
__device__ __forceinline__ float key2f(unsigned long long k) {
    uint32_t b = (uint32_t)(k >> 32);
    b = (b & 0x80000000u) ? (b & 0x7FFFFFFFu) : ~b;
    return __uint_as_float(b);
}

// ---------------- prep ----------------
__global__ void prep_split(const float* __restrict__ emb) {
    int i4 = (blockIdx.x * blockDim.x + threadIdx.x) * 4;
    float4 v = *(const float4*)(emb + i4);
    float vv[4] = {v.x, v.y, v.z, v.w};
    __half h[4];
#pragma unroll
    for (int j = 0; j < 4; j++) h[j] = __float2half_rn(vv[j]);
    *(uint2*)(g_Ehi + i4) = *(uint2*)h;
}
__global__ void prep_e2(const float* __restrict__ emb) {
    int k = blockIdx.x * blockDim.x + threadIdx.x;
    if (k < NCODES) {
        const float* row = emb + (size_t)k * KDIM;
        float s = 0.f;
#pragma unroll 8
        for (int i = 0; i < KDIM; i++) s += row[i] * row[i];
        g_e2[k] = s;
    }
}

// ---------------- main ----------------
__global__ __launch_bounds__(512, 2) void vq_mma_kernel(
    const float* __restrict__ z, const float* __restrict__ emb, float* __restrict__ out)
{
    extern __shared__ char sm[];
    const uint32_t sbase = (uint32_t)__cvta_generic_to_shared(sm);

    const int tid  = threadIdx.x;
    const int lane = tid & 31;
    const int wid  = tid >> 5;              // 16 warps
    const int wn   = wid & 1;
    const int wrow = (wid >> 1) * 16;       // 16-row slab
    const int gr   = lane >> 2;
    const int lc   = lane & 3;

    unsigned long long* minkey = (unsigned long long*)(sm + MK_OFF);
    unsigned* cnt = (unsigned*)(sm + CNT_OFF);
    int* lst = (int*)(sm + LST_OFF);

    if (tid < MCTA) { minkey[tid] = ~0ULL; cnt[tid] = 0u; }

    // ---- convert X slice fp32 -> fp16 hi into smem A ([m][k], stride ASTR)
    const int mbase = blockIdx.x * MCTA;
    const float* zt = z + ((size_t)(mbase >> 12) * KDIM * NPIX) + (mbase & (NPIX - 1));
    {
        const int m = tid & 127;
        const int q = tid >> 7;             // k range [q*64, q*64+64)
        char* arowh = sm + AHI_OFF + (size_t)m * (ASTR * 2);
#pragma unroll 4
        for (int j = 0; j < 32; j++) {
            int k0 = q * 64 + j * 2;
            float v0 = zt[(size_t)k0 * NPIX + m];
            float v1 = zt[(size_t)(k0 + 1) * NPIX + m];
            __half h0 = __float2half_rn(v0), h1 = __float2half_rn(v1);
            *(uint32_t*)(arowh + k0 * 2) =
                (uint32_t)__half_as_ushort(h0) | ((uint32_t)__half_as_ushort(h1) << 16);
        }
    }

    auto loadB = [&](int g) {
        int nch = g >> 2, kt = g & 3;
        uint32_t bb = sbase + B_OFF + (uint32_t)(g & 1) * BBUF_SZ;
#pragma unroll
        for (int j = 0; j < 2; j++) {
            int chunk = tid * 2 + j;        // 0..1023
            int row = chunk >> 3, ch = chunk & 7;
            const __half* src = g_Ehi + (size_t)(nch * 128 + row) * KDIM + kt * BK + ch * 8;
            cp16(bb + row * (BSTR * 2) + ch * 16, src);
        }
        CP_COMMIT();
    };

    loadB(0);
    __syncthreads();                         // conversion + init published

    const uint32_t a_lrow = (lane & 15);
    const uint32_t a_lq   = (lane >> 4) * 16;
    const uint32_t b_lrow = (lane & 7) + ((lane & 16) >> 1);
    const uint32_t b_lq   = ((lane >> 3) & 1) * 16;

    float c[8][4];

    for (int g = 0; g < NTILE; g++) {
        const int kt = g & 3, nch = g >> 2;
        if (kt == 0) {
#pragma unroll
            for (int ni = 0; ni < 8; ni++)
#pragma unroll
                for (int r = 0; r < 4; r++) c[ni][r] = 0.f;
        }

        if (g + 1 < NTILE) { loadB(g + 1); CP_WAIT1(); }
        else               { CP_WAIT0(); }
        __syncthreads();                     // buf g ready

        const uint32_t bbase = sbase + B_OFF + (uint32_t)(g & 1) * BBUF_SZ;
        const uint32_t akb   = (uint32_t)(kt * BK * 2);

#pragma unroll
        for (int k16 = 0; k16 < 4; k16++) {
            uint32_t af[4];
            ldmx4(af, sbase + AHI_OFF + (uint32_t)(wrow + a_lrow) * (ASTR * 2)
                      + akb + (uint32_t)k16 * 32 + a_lq);
#pragma unroll
            for (int ni2 = 0; ni2 < 4; ni2++) {      // only 4 B-frag regs live
                uint32_t bf[4];
                ldmx4(bf, bbase + (uint32_t)(wn * 64 + ni2 * 16 + b_lrow) * (BSTR * 2)
                          + (uint32_t)k16 * 32 + b_lq);
                mma16816(c[ni2 * 2 + 0], af, bf[0], bf[1]);
                mma16816(c[ni2 * 2 + 1], af, bf[2], bf[3]);
            }
        }
        __syncthreads();                     // buf g free before loadB(g+2) overwrite

        if (kt == 3) {
            // ---- screen: local row-min, merge with stale smem min, append
            unsigned long long kminr[2] = {~0ULL, ~0ULL};
#pragma unroll
            for (int ni = 0; ni < 8; ni++) {
#pragma unroll
                for (int cp = 0; cp < 2; cp++) {
                    int code = nch * 128 + wn * 64 + ni * 8 + lc * 2 + cp;
                    float e2v = __ldg(&g_e2[code]);
#pragma unroll
                    for (int rh = 0; rh < 2; rh++) {
                        unsigned long long k = dkey(fmaf(-2.f, c[ni][rh * 2 + cp], e2v), code);
                        if (k < kminr[rh]) kminr[rh] = k;
                    }
                }
            }
#pragma unroll
            for (int off = 1; off <= 2; off <<= 1) {
#pragma unroll
                for (int rh = 0; rh < 2; rh++) {
                    unsigned long long o = __shfl_xor_sync(0xffffffffu, kminr[rh], off);
                    if (o < kminr[rh]) kminr[rh] = o;
                }
            }
            int rowA = wrow + gr, rowB = wrow + gr + 8;
            unsigned long long sA = minkey[rowA], sB = minkey[rowB];   // stale, >= final min
            if (sA < kminr[0]) kminr[0] = sA;
            if (sB < kminr[1]) kminr[1] = sB;
            if (lc == 0) {
                atomicMin(&minkey[rowA], kminr[0]);
                atomicMin(&minkey[rowB], kminr[1]);
            }
            float thr0 = key2f(kminr[0]) + DELTA;
            float thr1 = key2f(kminr[1]) + DELTA;
#pragma unroll
            for (int ni = 0; ni < 8; ni++) {
#pragma unroll
                for (int cp = 0; cp < 2; cp++) {
                    int code = nch * 128 + wn * 64 + ni * 8 + lc * 2 + cp;
                    float e2v = __ldg(&g_e2[code]);
                    float d0 = fmaf(-2.f, c[ni][cp], e2v);
                    float d1 = fmaf(-2.f, c[ni][2 + cp], e2v);
                    if (d0 <= thr0) {
                        unsigned pos = atomicAdd(&cnt[rowA], 1u);
                        if (pos < LCAP) lst[rowA * LCAP + pos] = code;
                    }
                    if (d1 <= thr1) {
                        unsigned pos = atomicAdd(&cnt[rowB], 1u);
                        if (pos < LCAP) lst[rowB * LCAP + pos] = code;
                    }
                }
            }
        }
    }
    __syncthreads();                         // publish cnt/lst for rescue

    // ---- exact fp32 rescue: warp owns pixels wid*8..wid*8+7, x from gmem z
#pragma unroll 1
    for (int pi = 0; pi < 8; pi++) {
        int p = wid * 8 + pi;
        float xv[8];
#pragma unroll
        for (int j = 0; j < 8; j++)
            xv[j] = zt[(size_t)(lane * 8 + j) * NPIX + p];

        unsigned n = cnt[p];
        unsigned long long best = ~0ULL;
        if (n <= LCAP) {
            for (unsigned i = 0; i < n; i++) {
                int code = lst[p * LCAP + i];
                const float* e = emb + (size_t)code * KDIM + lane * 8;
                float4 e0 = *(const float4*)(e);
                float4 e1 = *(const float4*)(e + 4);
                float s = xv[0] * e0.x;
                s = fmaf(xv[1], e0.y, s); s = fmaf(xv[2], e0.z, s); s = fmaf(xv[3], e0.w, s);
                s = fmaf(xv[4], e1.x, s); s = fmaf(xv[5], e1.y, s);
                s = fmaf(xv[6], e1.z, s); s = fmaf(xv[7], e1.w, s);
#pragma unroll
                for (int off = 16; off > 0; off >>= 1)
                    s += __shfl_xor_sync(0xffffffffu, s, off);
                unsigned long long key = dkey(fmaf(-2.f, s, __ldg(&g_e2[code])), code);
                if (key < best) best = key;
            }
        } else {
            for (int code = 0; code < NCODES; code++) {
                const float* e = emb + (size_t)code * KDIM + lane * 8;
                float4 e0 = *(const float4*)(e);
                float4 e1 = *(const float4*)(e + 4);
                float s = xv[0] * e0.x;
                s = fmaf(xv[1], e0.y, s); s = fmaf(xv[2], e0.z, s); s = fmaf(xv[3], e0.w, s);
                s = fmaf(xv[4], e1.x, s); s = fmaf(xv[5], e1.y, s);
                s = fmaf(xv[6], e1.z, s); s = fmaf(xv[7], e1.w, s);
#pragma unroll
                for (int off = 16; off > 0; off >>= 1)
                    s += __shfl_xor_sync(0xffffffffu, s, off);
                unsigned long long key = dkey(fmaf(-2.f, s, __ldg(&g_e2[code])), code);
                if (key < best) best = key;
            }
        }
        if (lane == 0)
            out[mbase + p] = (float)(unsigned)(best & 0xFFFFFFFFull);
    }
}

extern "C" void kernel_launch(void* const* d_in, const int* in_sizes, int n_in,
                              void* d_out, int out_size) {
    const float* z;
    const float* emb;
    if (n_in >= 2 && in_sizes[1] > in_sizes[0]) {
        z = (const float*)d_in[1];  emb = (const float*)d_in[0];
    } else {
        z = (const float*)d_in[0];  emb = (const float*)d_in[n_in > 1 ? 1 : 0];
    }
    float* out = (float*)d_out;

    cudaFuncSetAttribute(vq_mma_kernel, cudaFuncAttributeMaxDynamicSharedMemorySize, SMEM_SZ);

    prep_split<<<256, 256>>>(emb);
    prep_e2<<<4, 256>>>(emb);
    vq_mma_kernel<<<65536 / MCTA, 512, SMEM_SZ>>>(z, emb, out);
}

// round 16
// speedup vs baseline: 1.3301x; 1.3301x over previous
#include <cuda_runtime.h>
#include <cuda_fp16.h>
#include <cstdint>

// CodeBook VQ argmin: one-pass HMMA screen with FP16 ACCUMULATORS + exact rescue.
// R16 = R14 structure; mma.m16n8k16.f16.f16.f16.f16 (potential 2x rate).
//   screen err: 16 chained fp16-accum roundings (<=~0.25 worst case) + hi-quant
//   0.016  =>  DELTA = 1.5 (>= 2*max err).  Superset-safety proof unchanged.
//   rescue: exact fp32 dot (x~ = hi+lo from smem, err 2^-22), tie -> lowest code.

#define NCODES 1024
#define KDIM   256
#define NPIX   4096
#define MCTA   128
#define DELTA  1.5f
#define LCAP   16

#define ASTR   264              // A row stride halves (528B)
#define BSTR   72               // B row stride halves (144B)
#define BK     64
#define NTILE  32               // 8 nchunks x 4 ktiles
#define BBUF_SZ 18432           // one B buffer

#define AHI_OFF   0             // 67584
#define ALO_OFF   67584         // 67584
#define B_OFF     135168        // 4 x 18432 = 73728
#define E2_OFF    208896        // 4096
#define MK_OFF    212992        // 1024
#define CNT_OFF   214016        // 512
#define LST_OFF   214528        // 8192
#define SMEM_SZ   222720

__device__ __align__(16) __half g_Ehi[NCODES * KDIM];
__device__ float g_e2[NCODES];

__device__ __forceinline__ void ldmx4(uint32_t* r, uint32_t addr) {
    asm volatile("ldmatrix.sync.aligned.m8n8.x4.shared.b16 {%0,%1,%2,%3}, [%4];"
                 : "=r"(r[0]), "=r"(r[1]), "=r"(r[2]), "=r"(r[3]) : "r"(addr));
}
// fp16-accumulator HMMA: D,C are 2 regs (4 halves): reg0 = row gr cols (c0,c1),
// reg1 = row gr+8 cols (c0,c1)
__device__ __forceinline__ void mma16816h(uint32_t* c, const uint32_t* a, uint32_t b0, uint32_t b1) {
    asm volatile("mma.sync.aligned.m16n8k16.row.col.f16.f16.f16.f16 "
                 "{%0,%1}, {%2,%3,%4,%5}, {%6,%7}, {%0,%1};"
                 : "+r"(c[0]), "+r"(c[1])
                 : "r"(a[0]), "r"(a[1]), "r"(a[2]), "r"(a[3]), "r"(b0), "r"(b1));
}
__device__ __forceinline__ void cp16(uint32_t dst, const void* src) {
    asm volatile("cp.async.cg.shared.global [%0], [%1], 16;"
                 :: "r"(dst), "l"(__cvta_generic_to_global(src)) : "memory");
}
#define CP_COMMIT() asm volatile("cp.async.commit_group;" ::: "memory")
#define CP_WAIT1()  asm volatile("cp.async.wait_group 1;" ::: "memory")
#define CP_WAIT0()  asm volatile("cp.async.wait_group 0;" ::: "memory")

__device__ __forceinline__ unsigned long long dkey(float d, int code) {
    uint32_t b = __float_as_uint(d);
    b = (b & 0x80000000u) ? ~b : (b | 0x80000000u);
    return ((unsigned long long)b << 32) | (unsigned)code;
}
__device__ __forceinline__ float key2f(unsigned long long k) {
    uint32_t b = (uint32_t)(k >> 32);
    b = (b & 0x80000000u) ? (b & 0x7FFFFFFFu) : ~b;
    return __uint_as_float(b);
}

// ---------------- prep ----------------
__global__ void prep_split(const float* __restrict__ emb) {
    int i4 = (blockIdx.x * blockDim.x + threadIdx.x) * 4;
    float4 v = *(const float4*)(emb + i4);
    float vv[4] = {v.x, v.y, v.z, v.w};
    __half h[4];
#pragma unroll
    for (int j = 0; j < 4; j++) h[j] = __float2half_rn(vv[j]);
    *(uint2*)(g_Ehi + i4) = *(uint2*)h;
}
__global__ void prep_e2(const float* __restrict__ emb) {
    int k = blockIdx.x * blockDim.x + threadIdx.x;
    if (k < NCODES) {
        const float* row = emb + (size_t)k * KDIM;
        float s = 0.f;
#pragma unroll 8
        for (int i = 0; i < KDIM; i++) s += row[i] * row[i];
        g_e2[k] = s;
    }
}

// ---------------- main ----------------
__global__ __launch_bounds__(512, 1) void vq_mma_kernel(
    const float* __restrict__ z, const float* __restrict__ emb, float* __restrict__ out)
{
    extern __shared__ char sm[];
    const uint32_t sbase = (uint32_t)__cvta_generic_to_shared(sm);

    const int tid  = threadIdx.x;
    const int lane = tid & 31;
    const int wid  = tid >> 5;              // 16 warps
    const int wn   = wid & 1;
    const int wrow = (wid >> 1) * 16;       // 16-row slab
    const int gr   = lane >> 2;
    const int lc   = lane & 3;

    float* e2s = (float*)(sm + E2_OFF);
    unsigned long long* minkey = (unsigned long long*)(sm + MK_OFF);
    unsigned* cnt = (unsigned*)(sm + CNT_OFF);
    int* lst = (int*)(sm + LST_OFF);

    for (int i = tid; i < NCODES; i += 512) e2s[i] = g_e2[i];
    if (tid < MCTA) { minkey[tid] = ~0ULL; cnt[tid] = 0u; }

    // ---- convert X slice fp32 -> fp16 hi/lo into smem ([m][k], stride ASTR)
    const int mbase = blockIdx.x * MCTA;
    const float* zt = z + ((size_t)(mbase >> 12) * KDIM * NPIX) + (mbase & (NPIX - 1));
    {
        const int m = tid & 127;
        const int q = tid >> 7;             // k range [q*64, q*64+64)
        char* arowh = sm + AHI_OFF + (size_t)m * (ASTR * 2);
        char* arowl = sm + ALO_OFF + (size_t)m * (ASTR * 2);
#pragma unroll 4
        for (int j = 0; j < 32; j++) {
            int k0 = q * 64 + j * 2;
            float v0 = zt[(size_t)k0 * NPIX + m];
            float v1 = zt[(size_t)(k0 + 1) * NPIX + m];
            __half h0 = __float2half_rn(v0), h1 = __float2half_rn(v1);
            __half l0 = __float2half_rn(v0 - __half2float(h0));
            __half l1 = __float2half_rn(v1 - __half2float(h1));
            *(uint32_t*)(arowh + k0 * 2) =
                (uint32_t)__half_as_ushort(h0) | ((uint32_t)__half_as_ushort(h1) << 16);
            *(uint32_t*)(arowl + k0 * 2) =
                (uint32_t)__half_as_ushort(l0) | ((uint32_t)__half_as_ushort(l1) << 16);
        }
    }

    auto loadB = [&](int g) {
        int nch = g >> 2, kt = g & 3;
        uint32_t bb = sbase + B_OFF + (uint32_t)(g & 3) * BBUF_SZ;
#pragma unroll
        for (int j = 0; j < 2; j++) {
            int chunk = tid * 2 + j;        // 0..1023
            int row = chunk >> 3, ch = chunk & 7;
            const __half* src = g_Ehi + (size_t)(nch * 128 + row) * KDIM + kt * BK + ch * 8;
            cp16(bb + row * (BSTR * 2) + ch * 16, src);
        }
        CP_COMMIT();
    };

    loadB(0);
    loadB(1);
    __syncthreads();                         // conversion + init published

    const uint32_t a_lrow = (lane & 15);
    const uint32_t a_lq   = (lane >> 4) * 16;
    const uint32_t b_lrow = (lane & 7) + ((lane & 16) >> 1);
    const uint32_t b_lq   = ((lane >> 3) & 1) * 16;

    uint32_t c[8][2];                        // fp16x2 accumulators: [ni][rh]

    for (int g = 0; g < NTILE; g++) {
        const int kt = g & 3, nch = g >> 2;
        if (kt == 0) {
#pragma unroll
            for (int ni = 0; ni < 8; ni++) { c[ni][0] = 0u; c[ni][1] = 0u; }
        }

        if (g + 1 < NTILE) CP_WAIT1(); else CP_WAIT0();
        __syncthreads();                     // single barrier per tile: publish buf kt

        if (g + 2 < NTILE) loadB(g + 2);     // buf (g+2)&3 disjoint from readable bufs

        const uint32_t bbase = sbase + B_OFF + (uint32_t)kt * BBUF_SZ;
        const uint32_t akb   = (uint32_t)(kt * BK * 2);

#pragma unroll
        for (int k16 = 0; k16 < 4; k16++) {
            uint32_t af[4];
            ldmx4(af, sbase + AHI_OFF + (uint32_t)(wrow + a_lrow) * (ASTR * 2)
                      + akb + (uint32_t)k16 * 32 + a_lq);
            uint32_t bf[4][4];
#pragma unroll
            for (int ni2 = 0; ni2 < 4; ni2++)
                ldmx4(bf[ni2], bbase + (uint32_t)(wn * 64 + ni2 * 16 + b_lrow) * (BSTR * 2)
                               + (uint32_t)k16 * 32 + b_lq);
#pragma unroll
            for (int ni = 0; ni < 8; ni++)
                mma16816h(c[ni], af, bf[ni >> 1][(ni & 1) * 2], bf[ni >> 1][(ni & 1) * 2 + 1]);
        }

        if (kt == 3) {
            // ---- screen: unpack fp16 accum, local row-min, merge stale smem min, append
            float dv[8][2][2];               // [ni][rh][cp]
            unsigned long long kminr[2] = {~0ULL, ~0ULL};
#pragma unroll
            for (int ni = 0; ni < 8; ni++) {
                int code0 = nch * 128 + wn * 64 + ni * 8 + lc * 2;
                float e20 = e2s[code0], e21 = e2s[code0 + 1];
#pragma unroll
                for (int rh = 0; rh < 2; rh++) {
                    float2 sv = __half22float2(*(const __half2*)&c[ni][rh]);
                    float d0 = fmaf(-2.f, sv.x, e20);
                    float d1 = fmaf(-2.f, sv.y, e21);
                    dv[ni][rh][0] = d0; dv[ni][rh][1] = d1;
                    unsigned long long k0 = dkey(d0, code0);
                    unsigned long long k1 = dkey(d1, code0 + 1);
                    if (k0 < kminr[rh]) kminr[rh] = k0;
                    if (k1 < kminr[rh]) kminr[rh] = k1;
                }
            }
#pragma unroll
            for (int off = 1; off <= 2; off <<= 1) {
#pragma unroll
                for (int rh = 0; rh < 2; rh++) {
                    unsigned long long o = __shfl_xor_sync(0xffffffffu, kminr[rh], off);
                    if (o < kminr[rh]) kminr[rh] = o;
                }
            }
            int rowA = wrow + gr, rowB = wrow + gr + 8;
            unsigned long long sA = minkey[rowA], sB = minkey[rowB];   // stale, >= final min
            if (sA < kminr[0]) kminr[0] = sA;
            if (sB < kminr[1]) kminr[1] = sB;
            if (lc == 0) {
                atomicMin(&minkey[rowA], kminr[0]);
                atomicMin(&minkey[rowB], kminr[1]);
            }
            float thr0 = key2f(kminr[0]) + DELTA;
            float thr1 = key2f(kminr[1]) + DELTA;
#pragma unroll
            for (int ni = 0; ni < 8; ni++) {
                int code0 = nch * 128 + wn * 64 + ni * 8 + lc * 2;
#pragma unroll
                for (int cp = 0; cp < 2; cp++) {
                    if (dv[ni][0][cp] <= thr0) {
                        unsigned pos = atomicAdd(&cnt[rowA], 1u);
                        if (pos < LCAP) lst[rowA * LCAP + pos] = code0 + cp;
                    }
                    if (dv[ni][1][cp] <= thr1) {
                        unsigned pos = atomicAdd(&cnt[rowB], 1u);
                        if (pos < LCAP) lst[rowB * LCAP + pos] = code0 + cp;
                    }
                }
            }
        }
    }
    __syncthreads();                         // publish cnt/lst for rescue

    // ---- exact rescue: warp owns pixels wid*8..wid*8+7, x~ from smem hi+lo
#pragma unroll 1
    for (int pi = 0; pi < 8; pi++) {
        int p = wid * 8 + pi;
        uint4 rh4 = *(const uint4*)(sm + AHI_OFF + (size_t)p * (ASTR * 2) + lane * 16);
        uint4 rl4 = *(const uint4*)(sm + ALO_OFF + (size_t)p * (ASTR * 2) + lane * 16);
        float xv[8];
        {
            const uint32_t hw[4] = {rh4.x, rh4.y, rh4.z, rh4.w};
            const uint32_t lw[4] = {rl4.x, rl4.y, rl4.z, rl4.w};
#pragma unroll
            for (int q = 0; q < 4; q++) {
                __half2 h2 = *(const __half2*)&hw[q];
                __half2 l2 = *(const __half2*)&lw[q];
                float2 hf = __half22float2(h2), lf = __half22float2(l2);
                xv[q * 2 + 0] = hf.x + lf.x;
                xv[q * 2 + 1] = hf.y + lf.y;
            }
        }
        unsigned n = cnt[p];
        unsigned long long best = ~0ULL;
        if (n <= LCAP) {
            for (unsigned i = 0; i < n; i++) {
                int code = lst[p * LCAP + i];
                const float* e = emb + (size_t)code * KDIM + lane * 8;
                float4 e0 = *(const float4*)(e);
                float4 e1 = *(const float4*)(e + 4);
                float s = xv[0] * e0.x;
                s = fmaf(xv[1], e0.y, s); s = fmaf(xv[2], e0.z, s); s = fmaf(xv[3], e0.w, s);
                s = fmaf(xv[4], e1.x, s); s = fmaf(xv[5], e1.y, s);
                s = fmaf(xv[6], e1.z, s); s = fmaf(xv[7], e1.w, s);
#pragma unroll
                for (int off = 16; off > 0; off >>= 1)
                    s += __shfl_xor_sync(0xffffffffu, s, off);
                unsigned long long key = dkey(fmaf(-2.f, s, e2s[code]), code);
                if (key < best) best = key;
            }
        } else {
            for (int code = 0; code < NCODES; code++) {
                const float* e = emb + (size_t)code * KDIM + lane * 8;
                float4 e0 = *(const float4*)(e);
                float4 e1 = *(const float4*)(e + 4);
                float s = xv[0] * e0.x;
                s = fmaf(xv[1], e0.y, s); s = fmaf(xv[2], e0.z, s); s = fmaf(xv[3], e0.w, s);
                s = fmaf(xv[4], e1.x, s); s = fmaf(xv[5], e1.y, s);
                s = fmaf(xv[6], e1.z, s); s = fmaf(xv[7], e1.w, s);
#pragma unroll
                for (int off = 16; off > 0; off >>= 1)
                    s += __shfl_xor_sync(0xffffffffu, s, off);
                unsigned long long key = dkey(fmaf(-2.f, s, e2s[code]), code);
                if (key < best) best = key;
            }
        }
        if (lane == 0)
            out[mbase + p] = (float)(unsigned)(best & 0xFFFFFFFFull);
    }
}

extern "C" void kernel_launch(void* const* d_in, const int* in_sizes, int n_in,
                              void* d_out, int out_size) {
    const float* z;
    const float* emb;
    if (n_in >= 2 && in_sizes[1] > in_sizes[0]) {
        z = (const float*)d_in[1];  emb = (const float*)d_in[0];
    } else {
        z = (const float*)d_in[0];  emb = (const float*)d_in[n_in > 1 ? 1 : 0];
    }
    float* out = (float*)d_out;

    cudaFuncSetAttribute(vq_mma_kernel, cudaFuncAttributeMaxDynamicSharedMemorySize, SMEM_SZ);

    prep_split<<<256, 256>>>(emb);
    prep_e2<<<4, 256>>>(emb);
    vq_mma_kernel<<<65536 / MCTA, 512, SMEM_SZ>>>(z, emb, out);
}